// round 10
// baseline (speedup 1.0000x reference)
#include <cuda_runtime.h>
#include <cuda_bf16.h>
#include <cstdint>

typedef unsigned int u32;

// ---------------- global scratch ----------------
#define BTOT 131072
__device__ __align__(16) __nv_bfloat16 g_a1h[BTOT * 384];
__device__ __align__(16) __nv_bfloat16 g_a1l[BTOT * 384];
// fc1 weights: [2 pass][24 ch][128 n][40 k]  (ch 0-11 hi, 12-23 lo)
__device__ __align__(16) __nv_bfloat16 g_w1p[2 * 24 * 128 * 40];
// fc2 weights: [16 ch][64 n][40 k]  (ch 0-7 hi, 8-15 lo)
__device__ __align__(16) __nv_bfloat16 g_w2p[16 * 64 * 40];

__device__ __forceinline__ u32 smem_u32(const void* p) {
    u32 a; asm("{ .reg .u64 t; cvta.to.shared.u64 t, %1; cvt.u32.u64 %0, t; }" : "=r"(a) : "l"(p)); return a;
}
__device__ __forceinline__ void ldm4(u32 a, u32* d) {
    asm volatile("ldmatrix.sync.aligned.m8n8.x4.shared.b16 {%0,%1,%2,%3},[%4];"
                 : "=r"(d[0]), "=r"(d[1]), "=r"(d[2]), "=r"(d[3]) : "r"(a));
}
__device__ __forceinline__ void mma_bf16(float* d, const u32* a, u32 b0, u32 b1) {
    asm volatile("mma.sync.aligned.m16n8k16.row.col.f32.bf16.bf16.f32 "
                 "{%0,%1,%2,%3},{%4,%5,%6,%7},{%8,%9},{%0,%1,%2,%3};"
                 : "+f"(d[0]), "+f"(d[1]), "+f"(d[2]), "+f"(d[3])
                 : "r"(a[0]), "r"(a[1]), "r"(a[2]), "r"(a[3]), "r"(b0), "r"(b1));
}
__device__ __forceinline__ u32 split2(float a, float b, u32& lo) {
    __nv_bfloat16 ha = __float2bfloat16(a), hb = __float2bfloat16(b);
    float ra = a - __bfloat162float(ha), rb = b - __bfloat162float(hb);
    lo = ((u32)__bfloat16_as_ushort(__float2bfloat16(rb)) << 16)
       | (u32)__bfloat16_as_ushort(__float2bfloat16(ra));
    return ((u32)__bfloat16_as_ushort(hb) << 16) | (u32)__bfloat16_as_ushort(ha);
}
__device__ __forceinline__ void cp16(u32 dst, const void* src) {
    asm volatile("cp.async.ca.shared.global [%0],[%1],16;" :: "r"(dst), "l"(src));
}

// ---------------- prep: split + relayout weights ----------------
__global__ void prep_kernel(const float* __restrict__ fw1, const float* __restrict__ fw2) {
    int i = blockIdx.x * 256 + threadIdx.x;
    if (i < 2 * 24 * 128 * 40) {
        int p = i / 122880, r = i % 122880;
        int ch = r / 5120, r2 = r % 5120;
        int nl = r2 / 40, pos = r2 % 40;
        int n = p * 128 + nl;
        int k = (ch % 12) * 32 + pos;
        float v = (pos < 32 && k < 360) ? fw1[n * 360 + k] : 0.0f;
        __nv_bfloat16 h = __float2bfloat16(v);
        g_w1p[i] = (ch < 12) ? h : __float2bfloat16(v - __bfloat162float(h));
    }
    if (i < 16 * 64 * 40) {
        int ch = i / 2560, rem = i % 2560, n = rem / 40, pos = rem % 40;
        int k = (ch % 8) * 32 + pos;
        float v = (pos < 32) ? fw2[n * 256 + k] : 0.0f;
        __nv_bfloat16 h = __float2bfloat16(v);
        g_w2p[i] = (ch < 8) ? h : __float2bfloat16(v - __bfloat162float(h));
    }
}

// ---------------- featurize kernel: 32 samples/block ----------------
#define FS_SC 0
#define FS_SIG 896
#define FS_H 20096
#define FS_L 44672
#define SMB_F 69248

__global__ __launch_bounds__(256, 2)
void feat_kernel(const float* __restrict__ sig,
                 const float* __restrict__ w1, const float* __restrict__ b1,
                 const float* __restrict__ w2, const float* __restrict__ b2)
{
    extern __shared__ char smem[];
    const int tid = threadIdx.x, bx = blockIdx.x;
    float* SC = (float*)(smem + FS_SC);
    // consts: w1 0..44, b1 45..49, w2 50..199, b2 200..209
    for (int i = tid; i < 45; i += 256) SC[i] = w1[i];
    if (tid < 5)  SC[45 + tid] = b1[tid];
    for (int i = tid; i < 150; i += 256) SC[50 + i] = w2[i];
    if (tid < 10) SC[200 + tid] = b2[tid];
    {
        const float4* g = (const float4*)(sig + (size_t)bx * 32 * 150);
        float4* s4 = (float4*)(smem + FS_SIG);
        for (int i = tid; i < 32 * 150 / 4; i += 256) s4[i] = g[i];
    }
    __syncthreads();

    {
        const int s = tid & 31, t0 = (tid >> 5) * 5;
        const float* xs = (const float*)(smem + FS_SIG) + s * 150;
        float sd[3][9];
#pragma unroll
        for (int c = 0; c < 3; ++c) {
            float xr[18];
#pragma unroll
            for (int j = 0; j < 18; ++j) xr[j] = xs[(t0 + j) * 3 + c];
#pragma unroll
            for (int tt = 0; tt < 9; ++tt) {
                float s1 = 0.f, s2 = 0.f;
#pragma unroll
                for (int j = 0; j < 10; ++j) { float v = xr[tt + j]; s1 += v; s2 += v * v; }
                sd[c][tt] = sqrtf(fmaxf((s2 - s1 * s1 * 0.1f) * (1.0f / 9.0f), 0.f));
            }
        }
        float h1[5][7];
#pragma unroll
        for (int o = 0; o < 5; ++o) {
            float bb = SC[45 + o];
#pragma unroll
            for (int tt = 0; tt < 7; ++tt) h1[o][tt] = bb;
#pragma unroll
            for (int c = 0; c < 3; ++c)
#pragma unroll
                for (int k = 0; k < 3; ++k) {
                    float w = SC[o * 9 + c * 3 + k];   // conv1_w at SC[0..44]  (BUG FIX)
#pragma unroll
                    for (int tt = 0; tt < 7; ++tt) h1[o][tt] += w * sd[c][tt + k];
                }
#pragma unroll
            for (int tt = 0; tt < 7; ++tt) h1[o][tt] = fmaxf(h1[o][tt], 0.f);
        }
        __nv_bfloat16* Ah = (__nv_bfloat16*)(smem + FS_H);
        __nv_bfloat16* Al = (__nv_bfloat16*)(smem + FS_L);
#pragma unroll
        for (int o = 0; o < 10; ++o) {
            float a2[5];
            float bb = SC[200 + o];
#pragma unroll
            for (int tt = 0; tt < 5; ++tt) a2[tt] = bb;
#pragma unroll
            for (int i = 0; i < 5; ++i)
#pragma unroll
                for (int k = 0; k < 3; ++k) {
                    float w = SC[50 + o * 15 + i * 3 + k];
#pragma unroll
                    for (int tt = 0; tt < 5; ++tt) a2[tt] += w * h1[i][tt + k];
                }
#pragma unroll
            for (int tt = 0; tt < 5; ++tt)
                if (t0 + tt < 36) {
                    float v = fmaxf(a2[tt], 0.f);
                    int k = (t0 + tt) * 10 + o;
                    __nv_bfloat16 h = __float2bfloat16(v);
                    Ah[s * 384 + k] = h;
                    Al[s * 384 + k] = __float2bfloat16(v - __bfloat162float(h));
                }
        }
    }
    // zero K pad 360..383
    for (int i = tid; i < 32 * 24; i += 256) {
        int s = i / 24, k = 360 + i % 24;
        ((__nv_bfloat16*)(smem + FS_H))[s * 384 + k] = __float2bfloat16(0.f);
        ((__nv_bfloat16*)(smem + FS_L))[s * 384 + k] = __float2bfloat16(0.f);
    }
    __syncthreads();
    // coalesced copy out: plane = 32*384*2 B = 1536 uint4
    {
        const uint4* sh = (const uint4*)(smem + FS_H);
        const uint4* sl = (const uint4*)(smem + FS_L);
        uint4* gh = (uint4*)g_a1h + (size_t)bx * 1536;
        uint4* gl = (uint4*)g_a1l + (size_t)bx * 1536;
#pragma unroll
        for (int j = 0; j < 6; ++j) {
            gh[tid + j * 256] = sh[tid + j * 256];
            gl[tid + j * 256] = sl[tid + j * 256];
        }
    }
}

// ---------------- GEMM kernel: M=128, 512 threads ----------------
#define O_SC   0          // 1100 floats (SFB1 0, SFB2 256, SPW 320, SPB 1088)
#define O_A1H  4480       // 128 x 784 B
#define O_A1L  104832
#define O_W    205184     // 2 x 10240
#define SMB_G  225664
#define O_A2H  4480       // overlays A1 (after fc1 done)
#define O_A2L  72064
#define O_F2   139648     // 128 x 69 f32

__global__ __launch_bounds__(512)
void gemm_kernel(const float* __restrict__ fb1, const float* __restrict__ fb2,
                 const float* __restrict__ pw, const float* __restrict__ pb,
                 float* __restrict__ out)
{
    extern __shared__ char smem[];
    const int tid = threadIdx.x, lane = tid & 31, wid = tid >> 5, bx = blockIdx.x;
    const int g = lane >> 2, q = lane & 3;
    const int warpm = wid & 7, warpn = wid >> 3;
    const int lrow = lane & 7, lsel = lane >> 3;
    const u32 sb = smem_u32(smem);
    float* SC = (float*)(smem + O_SC);

    // SC staging
    for (int i = tid; i < 256; i += 512) SC[i] = fb1[i];
    if (tid < 64) SC[256 + tid] = fb2[tid];
    for (int i = tid; i < 768; i += 512) SC[320 + i] = pw[i];
    if (tid < 12) SC[1088 + tid] = pb[tid];

    // A1 prologue: cp.async both planes into padded [128][784B] layout
    {
        const __nv_bfloat16* gh = g_a1h + (size_t)bx * 128 * 384;
        const __nv_bfloat16* gl = g_a1l + (size_t)bx * 128 * 384;
#pragma unroll
        for (int it = 0; it < 12; ++it) {
            int i = tid + it * 512;
            int row = i / 48, seg = i % 48;
            cp16(sb + O_A1H + row * 784 + seg * 16, gh + row * 384 + seg * 8);
            cp16(sb + O_A1L + row * 784 + seg * 16, gl + row * 384 + seg * 8);
        }
        asm volatile("cp.async.commit_group;" ::: "memory");
    }
    // W stage 0 prefetch (registers)
    const uint4* wp1 = (const uint4*)g_w1p;   // 640 uint4 per stage
    uint4 wa, wb2 = make_uint4(0, 0, 0, 0);
    wa = wp1[tid];
    if (tid < 128) wb2 = wp1[512 + tid];
    asm volatile("cp.async.wait_group 0;" ::: "memory");
    {
        uint4* wb = (uint4*)(smem + O_W);
        wb[tid] = wa;
        if (tid < 128) wb[512 + tid] = wb2;
    }
    __syncthreads();

    // ldmatrix lane bases
    const u32 a1H = sb + O_A1H
        + (u32)((warpm * 16 + lrow + (lsel & 1) * 8) * 784 + ((lsel >> 1) & 1) * 16);
    const u32 a1L = a1H + (u32)(O_A1L - O_A1H);
    const u32 bOff = (u32)((warpn * 64 + lrow + ((lsel >> 1) & 1) * 8) * 80 + (lsel & 1) * 16);

    float acc[32];
#pragma unroll
    for (int i = 0; i < 32; ++i) acc[i] = 0.f;
    u32 ph0[16], pl0[16];

    // ---- fc1: 48 stages (2 passes x 24 chunks) ----
#pragma unroll 1
    for (int t = 0; t < 48; ++t) {
        if (t < 47) {
            const uint4* p = wp1 + (t + 1) * 640;
            wa = p[tid];
            if (tid < 128) wb2 = p[512 + tid];
        }
        const int ch = t % 24;
        const int kc = ch % 12;
        const bool both = (ch < 12);
        const u32 wbuf = sb + O_W + (u32)(t & 1) * 10240 + bOff;
#pragma unroll
        for (int ks = 0; ks < 2; ++ks) {
            const u32 ao = (u32)(kc * 64 + ks * 32);
            u32 ah[4], al[4];
            ldm4(a1H + ao, ah);
            if (both) ldm4(a1L + ao, al);
#pragma unroll
            for (int pr = 0; pr < 4; ++pr) {
                u32 b[4];
                ldm4(wbuf + pr * 1280 + ks * 32, b);
                mma_bf16(acc + pr * 8,     ah, b[0], b[1]);
                mma_bf16(acc + pr * 8 + 4, ah, b[2], b[3]);
                if (both) {
                    mma_bf16(acc + pr * 8,     al, b[0], b[1]);
                    mma_bf16(acc + pr * 8 + 4, al, b[2], b[3]);
                }
            }
        }
        if (t == 23) {
            // pass-0 epilogue: park in registers, reset acc
#pragma unroll
            for (int nt = 0; nt < 8; ++nt) {
                const int n = warpn * 64 + nt * 8 + q * 2;
                float b0 = SC[n], b1 = SC[n + 1];
                float v0 = fmaxf(acc[nt * 4 + 0] + b0, 0.f), v1 = fmaxf(acc[nt * 4 + 1] + b1, 0.f);
                float v2 = fmaxf(acc[nt * 4 + 2] + b0, 0.f), v3 = fmaxf(acc[nt * 4 + 3] + b1, 0.f);
                ph0[nt * 2]     = split2(v0, v1, pl0[nt * 2]);
                ph0[nt * 2 + 1] = split2(v2, v3, pl0[nt * 2 + 1]);
                acc[nt * 4] = acc[nt * 4 + 1] = acc[nt * 4 + 2] = acc[nt * 4 + 3] = 0.f;
            }
        }
        if (t < 47) {
            uint4* wb = (uint4*)(smem + O_W + ((t + 1) & 1) * 10240);
            wb[tid] = wa;
            if (tid < 128) wb[512 + tid] = wb2;
            __syncthreads();
        }
    }
    __syncthreads();   // all A1 reads complete before A2 overlays it

    // ---- write A2 (both passes), prefetch first W2 chunk ----
    {
        const int r0 = warpm * 16 + g;
#pragma unroll
        for (int nt = 0; nt < 8; ++nt) {
            const int nl = warpn * 64 + nt * 8 + q * 2;
            // pass 0 from park
            *(u32*)(smem + O_A2H + r0 * 528 + nl * 2)       = ph0[nt * 2];
            *(u32*)(smem + O_A2H + (r0 + 8) * 528 + nl * 2) = ph0[nt * 2 + 1];
            *(u32*)(smem + O_A2L + r0 * 528 + nl * 2)       = pl0[nt * 2];
            *(u32*)(smem + O_A2L + (r0 + 8) * 528 + nl * 2) = pl0[nt * 2 + 1];
            // pass 1 from live acc
            const int n = 128 + nl;
            float b0 = SC[n], b1 = SC[n + 1];
            float v0 = fmaxf(acc[nt * 4 + 0] + b0, 0.f), v1 = fmaxf(acc[nt * 4 + 1] + b1, 0.f);
            float v2 = fmaxf(acc[nt * 4 + 2] + b0, 0.f), v3 = fmaxf(acc[nt * 4 + 3] + b1, 0.f);
            u32 lo, hi;
            hi = split2(v0, v1, lo);
            *(u32*)(smem + O_A2H + r0 * 528 + n * 2) = hi;
            *(u32*)(smem + O_A2L + r0 * 528 + n * 2) = lo;
            hi = split2(v2, v3, lo);
            *(u32*)(smem + O_A2H + (r0 + 8) * 528 + n * 2) = hi;
            *(u32*)(smem + O_A2L + (r0 + 8) * 528 + n * 2) = lo;
        }
    }
    const uint4* wp2 = (const uint4*)g_w2p;   // 320 uint4 per chunk
    uint4 w2r = make_uint4(0, 0, 0, 0);
    if (tid < 320) w2r = wp2[tid];
    {
        uint4* wb = (uint4*)(smem + O_W);
        if (tid < 320) wb[tid] = w2r;
    }
    __syncthreads();

    // ---- fc2: 16 chunks, K=256, N=64 ----
#pragma unroll
    for (int i = 0; i < 16; ++i) acc[i] = 0.f;
    const u32 a2H = sb + O_A2H
        + (u32)((warpm * 16 + lrow + (lsel & 1) * 8) * 528 + ((lsel >> 1) & 1) * 16);
    const u32 a2L = a2H + (u32)(O_A2L - O_A2H);
    const u32 b2Off = (u32)((warpn * 32 + lrow + ((lsel >> 1) & 1) * 8) * 80 + (lsel & 1) * 16);

#pragma unroll 1
    for (int t = 0; t < 16; ++t) {
        if (t < 15) { if (tid < 320) w2r = wp2[(t + 1) * 320 + tid]; }
        const int kc = t % 8;
        const bool both = (t < 8);
        const u32 wbuf = sb + O_W + (u32)(t & 1) * 10240 + b2Off;
#pragma unroll
        for (int ks = 0; ks < 2; ++ks) {
            const u32 ao = (u32)(kc * 64 + ks * 32);
            u32 ah[4], al[4];
            ldm4(a2H + ao, ah);
            if (both) ldm4(a2L + ao, al);
#pragma unroll
            for (int pr = 0; pr < 2; ++pr) {
                u32 b[4];
                ldm4(wbuf + pr * 1280 + ks * 32, b);
                mma_bf16(acc + pr * 8,     ah, b[0], b[1]);
                mma_bf16(acc + pr * 8 + 4, ah, b[2], b[3]);
                if (both) {
                    mma_bf16(acc + pr * 8,     al, b[0], b[1]);
                    mma_bf16(acc + pr * 8 + 4, al, b[2], b[3]);
                }
            }
        }
        if (t < 15) {
            uint4* wb = (uint4*)(smem + O_W + ((t + 1) & 1) * 10240);
            if (tid < 320) wb[tid] = w2r;
            __syncthreads();
        }
    }

    // ---- fc2 epilogue -> F2 [128][69] (disjoint region) ----
    {
        float* f2 = (float*)(smem + O_F2);
        const int r0 = warpm * 16 + g;
#pragma unroll
        for (int nt = 0; nt < 4; ++nt) {
            const int n0 = warpn * 32 + nt * 8 + q * 2;
            float b0 = SC[256 + n0], b1 = SC[256 + n0 + 1];
            f2[r0 * 69 + n0]           = fmaxf(acc[nt * 4 + 0] + b0, 0.f);
            f2[r0 * 69 + n0 + 1]       = fmaxf(acc[nt * 4 + 1] + b1, 0.f);
            f2[(r0 + 8) * 69 + n0]     = fmaxf(acc[nt * 4 + 2] + b0, 0.f);
            f2[(r0 + 8) * 69 + n0 + 1] = fmaxf(acc[nt * 4 + 3] + b1, 0.f);
        }
    }
    __syncthreads();

    // ---- head (64->12) + log_softmax ----
    if (tid < 128) {
        const float* f2 = (const float*)(smem + O_F2) + tid * 69;
        float l[12];
#pragma unroll
        for (int j = 0; j < 12; ++j) l[j] = SC[1088 + j];
#pragma unroll 8
        for (int k = 0; k < 64; ++k) {
            float v = f2[k];
#pragma unroll
            for (int j = 0; j < 12; ++j) l[j] += v * SC[320 + j * 64 + k];
        }
        float m = l[0];
#pragma unroll
        for (int j = 1; j < 12; ++j) m = fmaxf(m, l[j]);
        float ssum = 0.f;
#pragma unroll
        for (int j = 0; j < 12; ++j) ssum += expf(l[j] - m);
        float lse = m + logf(ssum);
        float* op = out + ((size_t)bx * 128 + tid) * 12;
#pragma unroll
        for (int j = 0; j < 12; ++j) op[j] = l[j] - lse;
    }
}

extern "C" void kernel_launch(void* const* d_in, const int* in_sizes, int n_in,
                              void* d_out, int out_size)
{
    (void)n_in; (void)out_size;
    const float* sig = (const float*)d_in[0];
    const float* w1  = (const float*)d_in[1];
    const float* b1  = (const float*)d_in[2];
    const float* w2  = (const float*)d_in[3];
    const float* b2  = (const float*)d_in[4];
    const float* fw1 = (const float*)d_in[5];
    const float* fb1 = (const float*)d_in[6];
    const float* fw2 = (const float*)d_in[7];
    const float* fb2 = (const float*)d_in[8];
    const float* pw  = (const float*)d_in[9];
    const float* pb  = (const float*)d_in[10];
    float* out = (float*)d_out;

    const int B = in_sizes[0] / 150;
    prep_kernel<<<960, 256>>>(fw1, fw2);
    cudaFuncSetAttribute(feat_kernel, cudaFuncAttributeMaxDynamicSharedMemorySize, SMB_F);
    feat_kernel<<<B / 32, 256, SMB_F>>>(sig, w1, b1, w2, b2);
    cudaFuncSetAttribute(gemm_kernel, cudaFuncAttributeMaxDynamicSharedMemorySize, SMB_G);
    gemm_kernel<<<B / 128, 512, SMB_G>>>(fb1, fb2, pw, pb, out);
}

// round 11
// speedup vs baseline: 1.7770x; 1.7770x over previous
#include <cuda_runtime.h>
#include <cuda_bf16.h>
#include <cstdint>

typedef unsigned int u32;

#define NT 256
// smem byte offsets
#define O_SC   0
#define O_A1H  5376
#define O_A1L  55552
#define O_W    105728
#define O_A2H  5376
#define O_A2L  39168
#define O_F2   72960
#define SMB    146688
// const float indices
#define SW1 0
#define SB1 45
#define SW2 50
#define SB2 200
#define SFB1 210
#define SFB2 466
#define SPW 530
#define SPB 1298

// prep output: fc1 [24 chunks][256 n][40 k] (ch 0-11 hi, 12-23 lo), fc2 [16][64][40]
__device__ __align__(16) __nv_bfloat16 g_w1p[24 * 256 * 40];
__device__ __align__(16) __nv_bfloat16 g_w2p[16 * 64 * 40];

__device__ __forceinline__ u32 smem_u32(const void* p) {
    u32 a; asm("{ .reg .u64 t; cvta.to.shared.u64 t, %1; cvt.u32.u64 %0, t; }" : "=r"(a) : "l"(p)); return a;
}
__device__ __forceinline__ void ldm4(u32 a, u32* d) {
    asm volatile("ldmatrix.sync.aligned.m8n8.x4.shared.b16 {%0,%1,%2,%3},[%4];"
                 : "=r"(d[0]), "=r"(d[1]), "=r"(d[2]), "=r"(d[3]) : "r"(a));
}
__device__ __forceinline__ void mma_bf16(float* d, const u32* a, u32 b0, u32 b1) {
    asm volatile("mma.sync.aligned.m16n8k16.row.col.f32.bf16.bf16.f32 "
                 "{%0,%1,%2,%3},{%4,%5,%6,%7},{%8,%9},{%0,%1,%2,%3};"
                 : "+f"(d[0]), "+f"(d[1]), "+f"(d[2]), "+f"(d[3])
                 : "r"(a[0]), "r"(a[1]), "r"(a[2]), "r"(a[3]), "r"(b0), "r"(b1));
}
__device__ __forceinline__ u32 split2(float a, float b, u32& lo) {
    __nv_bfloat16 ha = __float2bfloat16(a), hb = __float2bfloat16(b);
    float ra = a - __bfloat162float(ha), rb = b - __bfloat162float(hb);
    lo = ((u32)__bfloat16_as_ushort(__float2bfloat16(rb)) << 16)
       | (u32)__bfloat16_as_ushort(__float2bfloat16(ra));
    return ((u32)__bfloat16_as_ushort(hb) << 16) | (u32)__bfloat16_as_ushort(ha);
}
__device__ __forceinline__ float sqrt_fast(float x) {
    float r; asm("sqrt.approx.f32 %0,%1;" : "=f"(r) : "f"(x)); return r;
}

__global__ void prep_kernel(const float* __restrict__ fw1, const float* __restrict__ fw2) {
    int i = blockIdx.x * 256 + threadIdx.x;
    if (i < 24 * 256 * 40) {
        int ch = i / 10240, rem = i % 10240, n = rem / 40, pos = rem % 40;
        int k = (ch % 12) * 32 + pos;
        float v = (pos < 32 && k < 360) ? fw1[n * 360 + k] : 0.0f;
        __nv_bfloat16 h = __float2bfloat16(v);
        g_w1p[i] = (ch < 12) ? h : __float2bfloat16(v - __bfloat162float(h));
    }
    if (i < 16 * 64 * 40) {
        int ch = i / 2560, rem = i % 2560, n = rem / 40, pos = rem % 40;
        int k = (ch % 8) * 32 + pos;
        float v = (pos < 32) ? fw2[n * 256 + k] : 0.0f;
        __nv_bfloat16 h = __float2bfloat16(v);
        g_w2p[i] = (ch < 8) ? h : __float2bfloat16(v - __bfloat162float(h));
    }
}

__global__ __launch_bounds__(NT, 1)
void convnet_mma_kernel(const float* __restrict__ sig,
                        const float* __restrict__ w1, const float* __restrict__ b1,
                        const float* __restrict__ w2, const float* __restrict__ b2,
                        const float* __restrict__ fb1, const float* __restrict__ fb2,
                        const float* __restrict__ pw, const float* __restrict__ pb,
                        float* __restrict__ out)
{
    extern __shared__ char smem[];
    const int tid = threadIdx.x, lane = tid & 31, wid = tid >> 5, bx = blockIdx.x;
    const int g = lane >> 2, q = lane & 3;
    const int warpm = wid & 3, warpn = wid >> 2;
    const int lrow = lane & 7, lsel = lane >> 3;
    const u32 sb = smem_u32(smem);
    float* SC = (float*)(smem + O_SC);

    // stage small consts
    for (int i = tid; i < 45; i += NT)  SC[SW1 + i] = w1[i];
    if (tid < 5)  SC[SB1 + tid] = b1[tid];
    for (int i = tid; i < 150; i += NT) SC[SW2 + i] = w2[i];
    if (tid < 10) SC[SB2 + tid] = b2[tid];
    SC[SFB1 + tid] = fb1[tid];
    if (tid < 64) SC[SFB2 + tid] = fb2[tid];
    for (int i = tid; i < 768; i += NT) SC[SPW + i] = pw[i];
    if (tid < 12) SC[SPB + tid] = pb[tid];
    // stage signal tile (64 x 150 f32) into W region
    {
        const float4* gsig = (const float4*)(sig + (size_t)bx * 64 * 150);
        float4* s4 = (float4*)(smem + O_W);
        for (int i = tid; i < 64 * 150 / 4; i += NT) s4[i] = gsig[i];
    }
    __syncthreads();

    // ---- featurize -> A1 hi/lo bf16, row-major [64][392] ----
    {
        const int s = tid & 63, t0 = (tid >> 6) * 9;
        const float* xs = (const float*)(smem + O_W) + s * 150;
        float xv[3][23];
#pragma unroll
        for (int j = 0; j < 23; ++j)
#pragma unroll
            for (int c = 0; c < 3; ++c) xv[c][j] = xs[(t0 + j) * 3 + c];
        float sd[3][13];
#pragma unroll
        for (int c = 0; c < 3; ++c)
#pragma unroll
            for (int tt = 0; tt < 13; ++tt) {
                float s1 = 0.f, s2 = 0.f;
#pragma unroll
                for (int j = 0; j < 10; ++j) { float v = xv[c][tt + j]; s1 += v; s2 += v * v; }
                sd[c][tt] = sqrt_fast(fmaxf((s2 - s1 * s1 * 0.1f) * (1.0f / 9.0f), 0.f));
            }
        float h1[5][11];
#pragma unroll
        for (int o = 0; o < 5; ++o) {
            float bb = SC[SB1 + o];
#pragma unroll
            for (int tt = 0; tt < 11; ++tt) h1[o][tt] = bb;
#pragma unroll
            for (int c = 0; c < 3; ++c)
#pragma unroll
                for (int k = 0; k < 3; ++k) {
                    float w = SC[SW1 + o * 9 + c * 3 + k];
#pragma unroll
                    for (int tt = 0; tt < 11; ++tt) h1[o][tt] += w * sd[c][tt + k];
                }
#pragma unroll
            for (int tt = 0; tt < 11; ++tt) h1[o][tt] = fmaxf(h1[o][tt], 0.f);
        }
        __nv_bfloat16* A1h = (__nv_bfloat16*)(smem + O_A1H);
        __nv_bfloat16* A1l = (__nv_bfloat16*)(smem + O_A1L);
#pragma unroll
        for (int o = 0; o < 10; ++o) {
            float a2[9];
            float bb = SC[SB2 + o];
#pragma unroll
            for (int tt = 0; tt < 9; ++tt) a2[tt] = bb;
#pragma unroll
            for (int i = 0; i < 5; ++i)
#pragma unroll
                for (int k = 0; k < 3; ++k) {
                    float w = SC[SW2 + o * 15 + i * 3 + k];
#pragma unroll
                    for (int tt = 0; tt < 9; ++tt) a2[tt] += w * h1[i][tt + k];
                }
#pragma unroll
            for (int tt = 0; tt < 9; ++tt) {
                float v = fmaxf(a2[tt], 0.f);
                int k = (t0 + tt) * 10 + o;
                __nv_bfloat16 h = __float2bfloat16(v);
                A1h[s * 392 + k] = h;
                A1l[s * 392 + k] = __float2bfloat16(v - __bfloat162float(h));
            }
        }
    }
    // zero K pad 360..383
    for (int i = tid; i < 64 * 24; i += NT) {
        int s = i / 24, k = 360 + i % 24;
        ((__nv_bfloat16*)(smem + O_A1H))[s * 392 + k] = __float2bfloat16(0.f);
        ((__nv_bfloat16*)(smem + O_A1L))[s * 392 + k] = __float2bfloat16(0.f);
    }
    __syncthreads();

    // ---- fc1: 64x256, K=384, 3-term hi/lo, batched ldmatrix fragments ----
    float acc[64];
#pragma unroll
    for (int i = 0; i < 64; ++i) acc[i] = 0.f;

    const uint4* wp1 = (const uint4*)g_w1p;   // 1280 uint4 per chunk
    uint4 wr[5];
#pragma unroll
    for (int j = 0; j < 5; ++j) wr[j] = wp1[tid + j * 256];
    {
        uint4* wb = (uint4*)(smem + O_W);
#pragma unroll
        for (int j = 0; j < 5; ++j) wb[tid + j * 256] = wr[j];
    }
    __syncthreads();

    const u32 a1H = sb + O_A1H
        + (u32)((warpm * 16 + lrow + (lsel & 1) * 8) * 784 + ((lsel >> 1) & 1) * 16);
    const u32 a1L = a1H + (u32)(O_A1L - O_A1H);
    const u32 b1B = (u32)((warpn * 128 + lrow + ((lsel >> 1) & 1) * 8) * 80 + (lsel & 1) * 16);

#pragma unroll 1
    for (int ch = 0; ch < 24; ++ch) {
        if (ch < 23) {
            const uint4* p = wp1 + (ch + 1) * 1280;
#pragma unroll
            for (int j = 0; j < 5; ++j) wr[j] = p[tid + j * 256];
        }
        const u32 bb = sb + O_W + (u32)(ch & 1) * 20480 + b1B;
        const u32 kof2 = (u32)(((ch < 12) ? ch : (ch - 12)) * 64);
        const bool both = (ch < 12);
#pragma unroll
        for (int ks = 0; ks < 2; ++ks) {
            u32 ah[4], al[4];
            ldm4(a1H + kof2 + ks * 32, ah);
            if (both) ldm4(a1L + kof2 + ks * 32, al);
            // batch ALL B fragments first so LDSM latencies overlap
            u32 bf[8][4];
#pragma unroll
            for (int pr = 0; pr < 8; ++pr) ldm4(bb + pr * 1280 + ks * 32, bf[pr]);
#pragma unroll
            for (int pr = 0; pr < 8; ++pr) {
                mma_bf16(acc + pr * 8,     ah, bf[pr][0], bf[pr][1]);
                mma_bf16(acc + pr * 8 + 4, ah, bf[pr][2], bf[pr][3]);
            }
            if (both) {
#pragma unroll
                for (int pr = 0; pr < 8; ++pr) {
                    mma_bf16(acc + pr * 8,     al, bf[pr][0], bf[pr][1]);
                    mma_bf16(acc + pr * 8 + 4, al, bf[pr][2], bf[pr][3]);
                }
            }
        }
        if (ch < 23) {
            uint4* wb = (uint4*)(smem + O_W + ((ch + 1) & 1) * 20480);
#pragma unroll
            for (int j = 0; j < 5; ++j) wb[tid + j * 256] = wr[j];
            __syncthreads();
        }
    }
    __syncthreads();   // all warps done reading A1 before A2 overwrites it

    // ---- fc1 epilogue: bias+relu+split -> A2 hi/lo [64][264] ----
    {
        const int r0 = warpm * 16 + g;
#pragma unroll
        for (int nt = 0; nt < 16; ++nt) {
            const int n0 = warpn * 128 + nt * 8 + q * 2;
            float bb0 = SC[SFB1 + n0], bb1 = SC[SFB1 + n0 + 1];
            float v0 = fmaxf(acc[nt * 4 + 0] + bb0, 0.f), v1 = fmaxf(acc[nt * 4 + 1] + bb1, 0.f);
            float v2 = fmaxf(acc[nt * 4 + 2] + bb0, 0.f), v3 = fmaxf(acc[nt * 4 + 3] + bb1, 0.f);
            u32 lo, hi;
            hi = split2(v0, v1, lo);
            *(u32*)(smem + O_A2H + r0 * 528 + n0 * 2) = hi;
            *(u32*)(smem + O_A2L + r0 * 528 + n0 * 2) = lo;
            hi = split2(v2, v3, lo);
            *(u32*)(smem + O_A2H + (r0 + 8) * 528 + n0 * 2) = hi;
            *(u32*)(smem + O_A2L + (r0 + 8) * 528 + n0 * 2) = lo;
        }
    }
    __syncthreads();

    // ---- fc2: 64x64, K=256, 3-term ----
#pragma unroll
    for (int i = 0; i < 16; ++i) acc[i] = 0.f;
    const uint4* wp2 = (const uint4*)g_w2p;   // 320 uint4 per chunk
    uint4 w2a; uint4 w2b = make_uint4(0, 0, 0, 0);
    w2a = wp2[tid];
    if (tid < 64) w2b = wp2[256 + tid];
    {
        uint4* wb = (uint4*)(smem + O_W);
        wb[tid] = w2a;
        if (tid < 64) wb[256 + tid] = w2b;
    }
    __syncthreads();

    const u32 a2H = sb + O_A2H
        + (u32)((warpm * 16 + lrow + (lsel & 1) * 8) * 528 + ((lsel >> 1) & 1) * 16);
    const u32 a2L = a2H + (u32)(O_A2L - O_A2H);
    const u32 b2B = (u32)((warpn * 32 + lrow + ((lsel >> 1) & 1) * 8) * 80 + (lsel & 1) * 16);

#pragma unroll 1
    for (int ch = 0; ch < 16; ++ch) {
        if (ch < 15) {
            const uint4* p = wp2 + (ch + 1) * 320;
            w2a = p[tid];
            if (tid < 64) w2b = p[256 + tid];
        }
        const u32 bb = sb + O_W + (u32)(ch & 1) * 20480 + b2B;
        const u32 kof2 = (u32)((ch & 7) * 64);
        const bool both = (ch < 8);
#pragma unroll
        for (int ks = 0; ks < 2; ++ks) {
            u32 ah[4], al[4];
            ldm4(a2H + kof2 + ks * 32, ah);
            if (both) ldm4(a2L + kof2 + ks * 32, al);
            u32 bf[2][4];
#pragma unroll
            for (int pr = 0; pr < 2; ++pr) ldm4(bb + pr * 1280 + ks * 32, bf[pr]);
#pragma unroll
            for (int pr = 0; pr < 2; ++pr) {
                mma_bf16(acc + pr * 8,     ah, bf[pr][0], bf[pr][1]);
                mma_bf16(acc + pr * 8 + 4, ah, bf[pr][2], bf[pr][3]);
            }
            if (both) {
#pragma unroll
                for (int pr = 0; pr < 2; ++pr) {
                    mma_bf16(acc + pr * 8,     al, bf[pr][0], bf[pr][1]);
                    mma_bf16(acc + pr * 8 + 4, al, bf[pr][2], bf[pr][3]);
                }
            }
        }
        if (ch < 15) {
            uint4* wb = (uint4*)(smem + O_W + ((ch + 1) & 1) * 20480);
            wb[tid] = w2a;
            if (tid < 64) wb[256 + tid] = w2b;
            __syncthreads();
        }
    }

    // ---- fc2 epilogue -> f2 [64][69] f32 ----
    {
        float* f2 = (float*)(smem + O_F2);
        const int r0 = warpm * 16 + g;
#pragma unroll
        for (int nt = 0; nt < 4; ++nt) {
            const int n0 = warpn * 32 + nt * 8 + q * 2;
            float bb0 = SC[SFB2 + n0], bb1 = SC[SFB2 + n0 + 1];
            f2[r0 * 69 + n0]           = fmaxf(acc[nt * 4 + 0] + bb0, 0.f);
            f2[r0 * 69 + n0 + 1]       = fmaxf(acc[nt * 4 + 1] + bb1, 0.f);
            f2[(r0 + 8) * 69 + n0]     = fmaxf(acc[nt * 4 + 2] + bb0, 0.f);
            f2[(r0 + 8) * 69 + n0 + 1] = fmaxf(acc[nt * 4 + 3] + bb1, 0.f);
        }
    }
    __syncthreads();

    // ---- head (64->12) + log_softmax ----
    if (tid < 64) {
        const float* f2 = (const float*)(smem + O_F2) + tid * 69;
        float l[12];
#pragma unroll
        for (int j = 0; j < 12; ++j) l[j] = SC[SPB + j];
#pragma unroll 8
        for (int k = 0; k < 64; ++k) {
            float v = f2[k];
#pragma unroll
            for (int j = 0; j < 12; ++j) l[j] += v * SC[SPW + j * 64 + k];
        }
        float m = l[0];
#pragma unroll
        for (int j = 1; j < 12; ++j) m = fmaxf(m, l[j]);
        float ssum = 0.f;
#pragma unroll
        for (int j = 0; j < 12; ++j) ssum += expf(l[j] - m);
        float lse = m + logf(ssum);
        float* op = out + ((size_t)bx * 64 + tid) * 12;
#pragma unroll
        for (int j = 0; j < 12; ++j) op[j] = l[j] - lse;
    }
}

extern "C" void kernel_launch(void* const* d_in, const int* in_sizes, int n_in,
                              void* d_out, int out_size)
{
    (void)n_in; (void)out_size;
    const float* sig = (const float*)d_in[0];
    const float* w1  = (const float*)d_in[1];
    const float* b1  = (const float*)d_in[2];
    const float* w2  = (const float*)d_in[3];
    const float* b2  = (const float*)d_in[4];
    const float* fw1 = (const float*)d_in[5];
    const float* fb1 = (const float*)d_in[6];
    const float* fw2 = (const float*)d_in[7];
    const float* fb2 = (const float*)d_in[8];
    const float* pw  = (const float*)d_in[9];
    const float* pb  = (const float*)d_in[10];
    float* out = (float*)d_out;

    const int B = in_sizes[0] / 150;
    prep_kernel<<<960, 256>>>(fw1, fw2);
    cudaFuncSetAttribute(convnet_mma_kernel, cudaFuncAttributeMaxDynamicSharedMemorySize, SMB);
    convnet_mma_kernel<<<B / 64, NT, SMB>>>(sig, w1, b1, w2, b2, fb1, fb2, pw, pb, out);
}

// round 12
// speedup vs baseline: 3.7754x; 2.1246x over previous
#include <cuda_runtime.h>
#include <cuda_fp16.h>
#include <cstdint>

typedef unsigned int u32;

#define NT 256
// smem byte offsets
#define O_SC   0
#define O_A1   5376          // 64 x 784 B fp16 (K=384 padded, stride 392 halves)
#define O_A2   5376          // overlays A1 after fc1 (64 x 528 B)
#define O_W    55552         // 2 x 20480 W double buffer
#define O_F2   55552         // F2 overlays W buffer 0 after fc2
#define SMB    96512
// const float indices
#define SW1 0
#define SB1 45
#define SW2 50
#define SB2 200
#define SFB1 210
#define SFB2 466
#define SPW 530
#define SPB 1298

// prep: fc1 [12 ch][256 n][40 k] fp16, fc2 [8 ch][64 n][40 k] fp16
__device__ __align__(16) __half g_w1p[12 * 256 * 40];
__device__ __align__(16) __half g_w2p[8 * 64 * 40];

__device__ __forceinline__ u32 smem_u32(const void* p) {
    u32 a; asm("{ .reg .u64 t; cvta.to.shared.u64 t, %1; cvt.u32.u64 %0, t; }" : "=r"(a) : "l"(p)); return a;
}
__device__ __forceinline__ void ldm4(u32 a, u32* d) {
    asm volatile("ldmatrix.sync.aligned.m8n8.x4.shared.b16 {%0,%1,%2,%3},[%4];"
                 : "=r"(d[0]), "=r"(d[1]), "=r"(d[2]), "=r"(d[3]) : "r"(a));
}
__device__ __forceinline__ void mma_f16(float* d, const u32* a, u32 b0, u32 b1) {
    asm volatile("mma.sync.aligned.m16n8k16.row.col.f32.f16.f16.f32 "
                 "{%0,%1,%2,%3},{%4,%5,%6,%7},{%8,%9},{%0,%1,%2,%3};"
                 : "+f"(d[0]), "+f"(d[1]), "+f"(d[2]), "+f"(d[3])
                 : "r"(a[0]), "r"(a[1]), "r"(a[2]), "r"(a[3]), "r"(b0), "r"(b1));
}
__device__ __forceinline__ u32 pack2h(float a, float b) {
    return ((u32)__half_as_ushort(__float2half_rn(b)) << 16)
         | (u32)__half_as_ushort(__float2half_rn(a));
}
__device__ __forceinline__ float sqrt_fast(float x) {
    float r; asm("sqrt.approx.f32 %0,%1;" : "=f"(r) : "f"(x)); return r;
}
__device__ __forceinline__ void cp16(u32 dst, const void* src) {
    asm volatile("cp.async.ca.shared.global [%0],[%1],16;" :: "r"(dst), "l"(src));
}
#define CP_COMMIT() asm volatile("cp.async.commit_group;" ::: "memory")
#define CP_WAIT0()  asm volatile("cp.async.wait_group 0;" ::: "memory")

__global__ void prep_kernel(const float* __restrict__ fw1, const float* __restrict__ fw2) {
    int i = blockIdx.x * 256 + threadIdx.x;
    if (i < 12 * 256 * 40) {
        int ch = i / 10240, rem = i % 10240, n = rem / 40, pos = rem % 40;
        int k = ch * 32 + pos;
        float v = (pos < 32 && k < 360) ? fw1[n * 360 + k] : 0.0f;
        g_w1p[i] = __float2half_rn(v);
    }
    if (i < 8 * 64 * 40) {
        int ch = i / 2560, rem = i % 2560, n = rem / 40, pos = rem % 40;
        int k = ch * 32 + pos;
        g_w2p[i] = __float2half_rn((pos < 32) ? fw2[n * 256 + k] : 0.0f);
    }
}

__global__ __launch_bounds__(NT, 2)
void convnet_mma_kernel(const float* __restrict__ sig,
                        const float* __restrict__ w1, const float* __restrict__ b1,
                        const float* __restrict__ w2, const float* __restrict__ b2,
                        const float* __restrict__ fb1, const float* __restrict__ fb2,
                        const float* __restrict__ pw, const float* __restrict__ pb,
                        float* __restrict__ out)
{
    extern __shared__ char smem[];
    const int tid = threadIdx.x, lane = tid & 31, wid = tid >> 5, bx = blockIdx.x;
    const int g = lane >> 2, q = lane & 3;
    const int warpm = wid & 3, warpn = wid >> 2;
    const int lrow = lane & 7, lsel = lane >> 3;
    const u32 sb = smem_u32(smem);
    float* SC = (float*)(smem + O_SC);

    // stage small consts
    for (int i = tid; i < 45; i += NT)  SC[SW1 + i] = w1[i];
    if (tid < 5)  SC[SB1 + tid] = b1[tid];
    for (int i = tid; i < 150; i += NT) SC[SW2 + i] = w2[i];
    if (tid < 10) SC[SB2 + tid] = b2[tid];
    SC[SFB1 + tid] = fb1[tid];
    if (tid < 64) SC[SFB2 + tid] = fb2[tid];
    for (int i = tid; i < 768; i += NT) SC[SPW + i] = pw[i];
    if (tid < 12) SC[SPB + tid] = pb[tid];
    // stage signal tile (64 x 150 f32) into W region
    {
        const float4* gsig = (const float4*)(sig + (size_t)bx * 64 * 150);
        float4* s4 = (float4*)(smem + O_W);
        for (int i = tid; i < 64 * 150 / 4; i += NT) s4[i] = gsig[i];
    }
    __syncthreads();

    // ---- featurize -> A1 fp16, row-major [64][392] halves ----
    {
        const int s = tid & 63, t0 = (tid >> 6) * 9;
        const float* xs = (const float*)(smem + O_W) + s * 150;
        float sd[3][13];
#pragma unroll
        for (int c = 0; c < 3; ++c) {
            float xr[22];
#pragma unroll
            for (int j = 0; j < 22; ++j) xr[j] = xs[(t0 + j) * 3 + c];
#pragma unroll
            for (int tt = 0; tt < 13; ++tt) {
                float s1 = 0.f, s2 = 0.f;
#pragma unroll
                for (int j = 0; j < 10; ++j) { float v = xr[tt + j]; s1 += v; s2 += v * v; }
                sd[c][tt] = sqrt_fast(fmaxf((s2 - s1 * s1 * 0.1f) * (1.0f / 9.0f), 0.f));
            }
        }
        float h1[5][11];
#pragma unroll
        for (int o = 0; o < 5; ++o) {
            float bb = SC[SB1 + o];
#pragma unroll
            for (int tt = 0; tt < 11; ++tt) h1[o][tt] = bb;
#pragma unroll
            for (int c = 0; c < 3; ++c)
#pragma unroll
                for (int k = 0; k < 3; ++k) {
                    float w = SC[SW1 + o * 9 + c * 3 + k];
#pragma unroll
                    for (int tt = 0; tt < 11; ++tt) h1[o][tt] += w * sd[c][tt + k];
                }
#pragma unroll
            for (int tt = 0; tt < 11; ++tt) h1[o][tt] = fmaxf(h1[o][tt], 0.f);
        }
        __half* A1 = (__half*)(smem + O_A1);
#pragma unroll
        for (int o = 0; o < 10; ++o) {
            float a2[9];
            float bb = SC[SB2 + o];
#pragma unroll
            for (int tt = 0; tt < 9; ++tt) a2[tt] = bb;
#pragma unroll
            for (int i = 0; i < 5; ++i)
#pragma unroll
                for (int k = 0; k < 3; ++k) {
                    float w = SC[SW2 + o * 15 + i * 3 + k];
#pragma unroll
                    for (int tt = 0; tt < 9; ++tt) a2[tt] += w * h1[i][tt + k];
                }
#pragma unroll
            for (int tt = 0; tt < 9; ++tt)
                A1[s * 392 + (t0 + tt) * 10 + o] = __float2half_rn(fmaxf(a2[tt], 0.f));
        }
    }
    // zero K pad 360..383
    for (int i = tid; i < 64 * 24; i += NT) {
        int s = i / 24, k = 360 + i % 24;
        ((__half*)(smem + O_A1))[s * 392 + k] = __ushort_as_half((unsigned short)0);
    }

    // stage fc1 W chunk 0 via cp.async (overlaps featurize tail)
    {
        const char* src = (const char*)g_w1p;
#pragma unroll
        for (int j = 0; j < 5; ++j) {
            int idx = tid + j * 256;
            cp16(sb + O_W + idx * 16, src + idx * 16);
        }
        CP_COMMIT();
    }
    CP_WAIT0();
    __syncthreads();

    // ---- fc1: 64x256, K=384, single-term fp16 ----
    float acc[64];
#pragma unroll
    for (int i = 0; i < 64; ++i) acc[i] = 0.f;

    const u32 a1B = sb + O_A1
        + (u32)((warpm * 16 + lrow + (lsel & 1) * 8) * 784 + ((lsel >> 1) & 1) * 16);
    const u32 b1B = (u32)((warpn * 128 + lrow + ((lsel >> 1) & 1) * 8) * 80 + (lsel & 1) * 16);

#pragma unroll 1
    for (int ch = 0; ch < 12; ++ch) {
        if (ch < 11) {
            const char* src = (const char*)g_w1p + (ch + 1) * 20480;
            u32 dst = sb + O_W + (u32)((ch + 1) & 1) * 20480;
#pragma unroll
            for (int j = 0; j < 5; ++j) {
                int idx = tid + j * 256;
                cp16(dst + idx * 16, src + idx * 16);
            }
            CP_COMMIT();
        }
        const u32 bb = sb + O_W + (u32)(ch & 1) * 20480 + b1B;
        const u32 kof = (u32)(ch * 64);
#pragma unroll
        for (int ks = 0; ks < 2; ++ks) {
            u32 ah[4];
            ldm4(a1B + kof + ks * 32, ah);
            u32 bf[4][4];
#pragma unroll
            for (int pr = 0; pr < 4; ++pr) ldm4(bb + pr * 1280 + ks * 32, bf[pr]);
#pragma unroll
            for (int pr = 0; pr < 4; ++pr) {
                mma_f16(acc + pr * 8,     ah, bf[pr][0], bf[pr][1]);
                mma_f16(acc + pr * 8 + 4, ah, bf[pr][2], bf[pr][3]);
            }
#pragma unroll
            for (int pr = 0; pr < 4; ++pr) ldm4(bb + (pr + 4) * 1280 + ks * 32, bf[pr]);
#pragma unroll
            for (int pr = 0; pr < 4; ++pr) {
                mma_f16(acc + (pr + 4) * 8,     ah, bf[pr][0], bf[pr][1]);
                mma_f16(acc + (pr + 4) * 8 + 4, ah, bf[pr][2], bf[pr][3]);
            }
        }
        if (ch < 11) {
            CP_WAIT0();
            __syncthreads();
        }
    }
    __syncthreads();   // all warps done reading A1 before A2 overwrites it

    // ---- fc1 epilogue: bias+relu -> A2 fp16 [64][264] (stride 528 B) ----
    {
        const int r0 = warpm * 16 + g;
#pragma unroll
        for (int nt = 0; nt < 16; ++nt) {
            const int n0 = warpn * 128 + nt * 8 + q * 2;
            float bb0 = SC[SFB1 + n0], bb1 = SC[SFB1 + n0 + 1];
            float v0 = fmaxf(acc[nt * 4 + 0] + bb0, 0.f), v1 = fmaxf(acc[nt * 4 + 1] + bb1, 0.f);
            float v2 = fmaxf(acc[nt * 4 + 2] + bb0, 0.f), v3 = fmaxf(acc[nt * 4 + 3] + bb1, 0.f);
            *(u32*)(smem + O_A2 + r0 * 528 + n0 * 2)       = pack2h(v0, v1);
            *(u32*)(smem + O_A2 + (r0 + 8) * 528 + n0 * 2) = pack2h(v2, v3);
        }
    }
    // stage fc2 W chunk 0 (overlaps epilogue stores)
    {
        const char* src = (const char*)g_w2p;
        int idx = tid;
        cp16(sb + O_W + idx * 16, src + idx * 16);
        if (tid < 64) {
            idx = 256 + tid;
            cp16(sb + O_W + idx * 16, src + idx * 16);
        }
        CP_COMMIT();
    }
    CP_WAIT0();
    __syncthreads();

    // ---- fc2: 64x64, K=256, single-term fp16 ----
#pragma unroll
    for (int i = 0; i < 16; ++i) acc[i] = 0.f;
    const u32 a2B = sb + O_A2
        + (u32)((warpm * 16 + lrow + (lsel & 1) * 8) * 528 + ((lsel >> 1) & 1) * 16);
    const u32 b2B = (u32)((warpn * 32 + lrow + ((lsel >> 1) & 1) * 8) * 80 + (lsel & 1) * 16);

#pragma unroll 1
    for (int ch = 0; ch < 8; ++ch) {
        if (ch < 7) {
            const char* src = (const char*)g_w2p + (ch + 1) * 5120;
            u32 dst = sb + O_W + (u32)((ch + 1) & 1) * 20480;
            int idx = tid;
            cp16(dst + idx * 16, src + idx * 16);
            if (tid < 64) {
                idx = 256 + tid;
                cp16(dst + idx * 16, src + idx * 16);
            }
            CP_COMMIT();
        }
        const u32 bb = sb + O_W + (u32)(ch & 1) * 20480 + b2B;
        const u32 kof = (u32)(ch * 64);
#pragma unroll
        for (int ks = 0; ks < 2; ++ks) {
            u32 ah[4];
            ldm4(a2B + kof + ks * 32, ah);
            u32 bf[2][4];
#pragma unroll
            for (int pr = 0; pr < 2; ++pr) ldm4(bb + pr * 1280 + ks * 32, bf[pr]);
#pragma unroll
            for (int pr = 0; pr < 2; ++pr) {
                mma_f16(acc + pr * 8,     ah, bf[pr][0], bf[pr][1]);
                mma_f16(acc + pr * 8 + 4, ah, bf[pr][2], bf[pr][3]);
            }
        }
        if (ch < 7) {
            CP_WAIT0();
            __syncthreads();
        }
    }
    __syncthreads();   // chunk-7 buffer (buf 1) reads done; F2 goes to buf 0 region

    // ---- fc2 epilogue -> F2 [64][69] f32 at O_F2 (W buffer 0) ----
    {
        float* f2 = (float*)(smem + O_F2);
        const int r0 = warpm * 16 + g;
#pragma unroll
        for (int nt = 0; nt < 4; ++nt) {
            const int n0 = warpn * 32 + nt * 8 + q * 2;
            float bb0 = SC[SFB2 + n0], bb1 = SC[SFB2 + n0 + 1];
            f2[r0 * 69 + n0]           = fmaxf(acc[nt * 4 + 0] + bb0, 0.f);
            f2[r0 * 69 + n0 + 1]       = fmaxf(acc[nt * 4 + 1] + bb1, 0.f);
            f2[(r0 + 8) * 69 + n0]     = fmaxf(acc[nt * 4 + 2] + bb0, 0.f);
            f2[(r0 + 8) * 69 + n0 + 1] = fmaxf(acc[nt * 4 + 3] + bb1, 0.f);
        }
    }
    __syncthreads();

    // ---- head (64->12) + log_softmax ----
    if (tid < 64) {
        const float* f2 = (const float*)(smem + O_F2) + tid * 69;
        float l[12];
#pragma unroll
        for (int j = 0; j < 12; ++j) l[j] = SC[SPB + j];
#pragma unroll 8
        for (int k = 0; k < 64; ++k) {
            float v = f2[k];
#pragma unroll
            for (int j = 0; j < 12; ++j) l[j] += v * SC[SPW + j * 64 + k];
        }
        float m = l[0];
#pragma unroll
        for (int j = 1; j < 12; ++j) m = fmaxf(m, l[j]);
        float ssum = 0.f;
#pragma unroll
        for (int j = 0; j < 12; ++j) ssum += expf(l[j] - m);
        float lse = m + logf(ssum);
        float* op = out + ((size_t)bx * 64 + tid) * 12;
#pragma unroll
        for (int j = 0; j < 12; ++j) op[j] = l[j] - lse;
    }
}

extern "C" void kernel_launch(void* const* d_in, const int* in_sizes, int n_in,
                              void* d_out, int out_size)
{
    (void)n_in; (void)out_size;
    const float* sig = (const float*)d_in[0];
    const float* w1  = (const float*)d_in[1];
    const float* b1  = (const float*)d_in[2];
    const float* w2  = (const float*)d_in[3];
    const float* b2  = (const float*)d_in[4];
    const float* fw1 = (const float*)d_in[5];
    const float* fb1 = (const float*)d_in[6];
    const float* fw2 = (const float*)d_in[7];
    const float* fb2 = (const float*)d_in[8];
    const float* pw  = (const float*)d_in[9];
    const float* pb  = (const float*)d_in[10];
    float* out = (float*)d_out;

    const int B = in_sizes[0] / 150;
    prep_kernel<<<480, 256>>>(fw1, fw2);
    cudaFuncSetAttribute(convnet_mma_kernel, cudaFuncAttributeMaxDynamicSharedMemorySize, SMB);
    convnet_mma_kernel<<<B / 64, NT, SMB>>>(sig, w1, b1, w2, b2, fb1, fb2, pw, pb, out);
}